// round 16
// baseline (speedup 1.0000x reference)
#include <cuda_runtime.h>

#define NPTS   16384
#define NBATCH 2
#define NSEED  1024
#define NSEEDT (NBATCH*NSEED)          // 2048
#define OUTSZ  (NBATCH*256*NSEED*4)
#define UCAP   256                     // max union samples per seed (4*64)

// ---------------- scratch (__device__ globals; no allocation allowed) -------
__device__ __align__(16) float g_px[NBATCH][NPTS];
__device__ __align__(16) float g_py[NBATCH][NPTS];
__device__ __align__(16) float g_pz[NBATCH][NPTS];
__device__ float    g_uh[NSEEDT * UCAP];
__device__ float    g_uy[NSEEDT * UCAP];
__device__ float    g_uz[NSEEDT * UCAP];
__device__ unsigned char g_um[NSEEDT * UCAP];   // 4-bit depth membership mask
__device__ int      g_ucnt[NSEEDT];
__device__ unsigned g_wl[NSEEDT * UCAP + 64];   // worklist: seed<<8 | idx
__device__ int      g_total;
__device__ float    g_w1f[192],   g_b1f[64];
__device__ float    g_w2f[8192],  g_b2f[128];
__device__ float    g_w3f[32768], g_b3f[256];

// ---------------- f32x2 helpers ---------------------------------------------
typedef unsigned long long ull;
__device__ __forceinline__ ull fma2(ull a, ull b, ull c) {
    ull d; asm("fma.rn.f32x2 %0, %1, %2, %3;" : "=l"(d) : "l"(a), "l"(b), "l"(c)); return d;
}
__device__ __forceinline__ ull mul2(ull a, ull b) {
    ull d; asm("mul.rn.f32x2 %0, %1, %2;" : "=l"(d) : "l"(a), "l"(b)); return d;
}
__device__ __forceinline__ ull add2(ull a, ull b) {
    ull d; asm("add.rn.f32x2 %0, %1, %2;" : "=l"(d) : "l"(a), "l"(b)); return d;
}
__device__ __forceinline__ ull pack2(float x) {
    ull r; asm("mov.b64 %0, {%1, %1};" : "=l"(r) : "f"(x)); return r;
}
__device__ __forceinline__ float2 u2f(ull v) {
    float2 f; asm("mov.b64 {%0, %1}, %2;" : "=f"(f.x), "=f"(f.y) : "l"(v)); return f;
}

// ---------------- kernel 0: fold BN into weights, SoA transpose, zero out ---
__global__ void prep_kernel(
    const float* __restrict__ pc,
    const float* __restrict__ w1, const float* __restrict__ b1, const float* __restrict__ ga1,
    const float* __restrict__ be1, const float* __restrict__ m1, const float* __restrict__ v1,
    const float* __restrict__ w2, const float* __restrict__ b2, const float* __restrict__ ga2,
    const float* __restrict__ be2, const float* __restrict__ m2, const float* __restrict__ v2,
    const float* __restrict__ w3, const float* __restrict__ b3, const float* __restrict__ ga3,
    const float* __restrict__ be3, const float* __restrict__ m3, const float* __restrict__ v3,
    float* __restrict__ out)
{
    int tid = blockIdx.x * blockDim.x + threadIdx.x;
    int stride = gridDim.x * blockDim.x;
    for (int i = tid; i < 192; i += stride)   { int o = i / 3;  g_w1f[i] = w1[i] * (ga1[o] * rsqrtf(v1[o] + 1e-5f)); }
    for (int i = tid; i < 64; i += stride)    { float s = ga1[i] * rsqrtf(v1[i] + 1e-5f); g_b1f[i] = (b1[i] - m1[i]) * s + be1[i]; }
    for (int i = tid; i < 8192; i += stride)  { int o = i >> 6; g_w2f[i] = w2[i] * (ga2[o] * rsqrtf(v2[o] + 1e-5f)); }
    for (int i = tid; i < 128; i += stride)   { float s = ga2[i] * rsqrtf(v2[i] + 1e-5f); g_b2f[i] = (b2[i] - m2[i]) * s + be2[i]; }
    for (int i = tid; i < 32768; i += stride) { int o = i >> 7; g_w3f[i] = w3[i] * (ga3[o] * rsqrtf(v3[o] + 1e-5f)); }
    for (int i = tid; i < 256; i += stride)   { float s = ga3[i] * rsqrtf(v3[i] + 1e-5f); g_b3f[i] = (b3[i] - m3[i]) * s + be3[i]; }
    for (int i = tid; i < NBATCH * NPTS; i += stride) {
        int b = i >> 14, n = i & (NPTS - 1);
        const float* p = pc + (size_t)i * 3;
        g_px[b][n] = p[0]; g_py[b][n] = p[1]; g_pz[b][n] = p[2];
    }
    for (int i = tid; i < OUTSZ; i += stride) out[i] = 0.0f;
}

// ---------------- kernel 1: 16 seeds/block, f32x2 paired-point scan ---------
// 128 blocks (single wave). Each warp scans its seed in index order with
// global counters; 2 points per lane via f32x2; even/odd ballots keep exact
// per-depth rank<64 semantics identical to the reference top_k selection.
#define GW   16
#define CH2  1024                      // float2 pairs per chunk (2048 points)
__global__ void __launch_bounds__(512) group_kernel(
    const float* __restrict__ seed_xyz, const float* __restrict__ vp_rot)
{
    __shared__ float2 chx[CH2], chy[CH2], chz[CH2];
    __shared__ int sDone;
    int tid = threadIdx.x, lane = tid & 31, w = tid >> 5;
    int seed = blockIdx.x * GW + w;            // batch-aligned (1024 % 16 == 0)
    int b = seed >> 10;

    const float* sp = seed_xyz + (size_t)seed * 3;
    float sx = sp[0], sy = sp[1], sz = sp[2];
    const float* R = vp_rot + (size_t)seed * 9;
    float r00 = R[0], r01 = R[1], r02 = R[2];
    float r10 = R[3], r11 = R[4], r12 = R[5];
    float r20 = R[6], r21 = R[7], r22 = R[8];
    ull NSX = pack2(-sx), NSY = pack2(-sy), NSZ = pack2(-sz);
    ull R00 = pack2(r00), R01 = pack2(r01), R02 = pack2(r02);
    ull R10 = pack2(r10), R11 = pack2(r11), R12 = pack2(r12);
    ull R20 = pack2(r20), R21 = pack2(r21), R22 = pack2(r22);

    const float2* __restrict__ px2 = (const float2*)g_px[b];
    const float2* __restrict__ py2 = (const float2*)g_py[b];
    const float2* __restrict__ pz2 = (const float2*)g_pz[b];

    if (tid == 0) sDone = 0;
    int c0 = 0, c1 = 0, c2 = 0, c3 = 0, u = 0;
    bool done = false;
    unsigned lm = (1u << lane) - 1u;
    unsigned lme = lm | (1u << lane);
    int gbase = seed * UCAP;

    for (int base2 = 0; base2 < NPTS / 2; base2 += CH2) {
        __syncthreads();                 // chunk reuse + sDone visibility
        if (sDone == GW) break;
        for (int i = tid; i < CH2; i += 512) {
            chx[i] = px2[base2 + i]; chy[i] = py2[base2 + i]; chz[i] = pz2[base2 + i];
        }
        __syncthreads();
        if (done) continue;

        ull nx = *(const ull*)&chx[lane], ny = *(const ull*)&chy[lane], nz = *(const ull*)&chz[lane];
        for (int it = 0; it < CH2; it += 32) {
            ull X = nx, Y = ny, Z = nz;
            int ip = (it + 32 < CH2) ? (it + 32 + lane) : lane;
            nx = *(const ull*)&chx[ip]; ny = *(const ull*)&chy[ip]; nz = *(const ull*)&chz[ip];

            ull dx = add2(X, NSX), dy = add2(Y, NSY), dz = add2(Z, NSZ);
            ull H2 = fma2(dz, R20, fma2(dy, R10, mul2(dx, R00)));
            ull Y2 = fma2(dz, R21, fma2(dy, R11, mul2(dx, R01)));
            ull Z2 = fma2(dz, R22, fma2(dy, R12, mul2(dx, R02)));
            ull RS = fma2(Z2, Z2, mul2(Y2, Y2));
            float2 hh = u2f(H2), rr = u2f(RS);
            bool ba = (rr.x < 0.0025f) && (hh.x > -0.02f) && (hh.x < 0.04f);
            bool bb = (rr.y < 0.0025f) && (hh.y > -0.02f) && (hh.y < 0.04f);
            unsigned any = __ballot_sync(0xffffffffu, ba || bb);
            if (!any) continue;

            unsigned e0 = __ballot_sync(0xffffffffu, ba && hh.x < 0.01f);
            unsigned o0 = __ballot_sync(0xffffffffu, bb && hh.y < 0.01f);
            unsigned e1 = __ballot_sync(0xffffffffu, ba && hh.x < 0.02f);
            unsigned o1 = __ballot_sync(0xffffffffu, bb && hh.y < 0.02f);
            unsigned e2 = __ballot_sync(0xffffffffu, ba && hh.x < 0.03f);
            unsigned o2 = __ballot_sync(0xffffffffu, bb && hh.y < 0.03f);
            unsigned e3 = __ballot_sync(0xffffffffu, ba);
            unsigned o3 = __ballot_sync(0xffffffffu, bb);

            int bitsa = 0, bitsb = 0;
            if (ba) {
                if (hh.x < 0.01f && c0 + __popc(e0 & lm) + __popc(o0 & lm) < 64) bitsa |= 1;
                if (hh.x < 0.02f && c1 + __popc(e1 & lm) + __popc(o1 & lm) < 64) bitsa |= 2;
                if (hh.x < 0.03f && c2 + __popc(e2 & lm) + __popc(o2 & lm) < 64) bitsa |= 4;
                if (               c3 + __popc(e3 & lm) + __popc(o3 & lm) < 64) bitsa |= 8;
            }
            if (bb) {
                if (hh.y < 0.01f && c0 + __popc(e0 & lme) + __popc(o0 & lm) < 64) bitsb |= 1;
                if (hh.y < 0.02f && c1 + __popc(e1 & lme) + __popc(o1 & lm) < 64) bitsb |= 2;
                if (hh.y < 0.03f && c2 + __popc(e2 & lme) + __popc(o2 & lm) < 64) bitsb |= 4;
                if (               c3 + __popc(e3 & lme) + __popc(o3 & lm) < 64) bitsb |= 8;
            }
            unsigned bea = __ballot_sync(0xffffffffu, bitsa != 0);
            unsigned beb = __ballot_sync(0xffffffffu, bitsb != 0);
            if (bitsa) {
                int s = gbase + u + __popc(bea & lm);
                float2 yv = u2f(Y2), zv = u2f(Z2);
                g_uh[s] = hh.x; g_uy[s] = yv.x; g_uz[s] = zv.x;
                g_um[s] = (unsigned char)bitsa;
            }
            if (bitsb) {
                int s = gbase + u + __popc(bea) + __popc(beb & lm);
                float2 yv = u2f(Y2), zv = u2f(Z2);
                g_uh[s] = hh.y; g_uy[s] = yv.y; g_uz[s] = zv.y;
                g_um[s] = (unsigned char)bitsb;
            }
            u  += __popc(bea) + __popc(beb);
            c0 += __popc(e0) + __popc(o0); c1 += __popc(e1) + __popc(o1);
            c2 += __popc(e2) + __popc(o2); c3 += __popc(e3) + __popc(o3);
            if (c0 >= 64) {                    // nested masks: all caps hit
                done = true;
                if (lane == 0) atomicAdd(&sDone, 1);
                break;
            }
        }
    }

    // fallback: empty depths use d_rot of point 0 (reference pads with idx 0)
    int ebits = (c0 == 0 ? 1 : 0) | (c1 == 0 ? 2 : 0) | (c2 == 0 ? 4 : 0) | (c3 == 0 ? 8 : 0);
    if (ebits) {
        if (lane == 0) {
            float fdx = g_px[b][0] - sx, fdy = g_py[b][0] - sy, fdz = g_pz[b][0] - sz;
            int s = gbase + u;
            g_uh[s] = fdx * r00 + fdy * r10 + fdz * r20;
            g_uy[s] = fdx * r01 + fdy * r11 + fdz * r21;
            g_uz[s] = fdx * r02 + fdy * r12 + fdz * r22;
            g_um[s] = (unsigned char)ebits;
        }
        u++;
    }
    if (lane == 0) g_ucnt[seed] = u;
}

// ---------------- kernel 1.5: pack worklist, seeds padded to 4-col units ----
__global__ void __launch_bounds__(1024) pack_kernel()
{
    __shared__ int soff[NSEEDT];
    __shared__ int wsum[32];
    int tid = threadIdx.x, lane = tid & 31, w = tid >> 5;

    int cA = (g_ucnt[2 * tid]     + 3) & ~3;
    int cB = (g_ucnt[2 * tid + 1] + 3) & ~3;
    int s = cA + cB;
    int v = s;
#pragma unroll
    for (int o = 1; o < 32; o <<= 1) { int t = __shfl_up_sync(0xffffffffu, v, o); if (lane >= o) v += t; }
    if (lane == 31) wsum[w] = v;
    __syncthreads();
    if (tid < 32) {
        int t = wsum[tid];
#pragma unroll
        for (int o = 1; o < 32; o <<= 1) { int x = __shfl_up_sync(0xffffffffu, t, o); if (tid >= o) t += x; }
        wsum[tid] = t;
    }
    __syncthreads();
    int excl = v - s + (w ? wsum[w - 1] : 0);
    soff[2 * tid] = excl; soff[2 * tid + 1] = excl + cA;
    __syncthreads();

    int total = wsum[31];
    for (int seed = tid; seed < NSEEDT; seed += 1024) {
        int basep = soff[seed], cnt = g_ucnt[seed], pc = (cnt + 3) & ~3;
        for (int p = 0; p < pc; p++) {
            int idx = p < cnt ? p : cnt - 1;   // dup pad == identity for max
            g_wl[basep + p] = (unsigned)((seed << 8) | idx);
        }
    }
    int tot64 = (total + 63) & ~63;
    for (int i = total + tid; i < tot64; i += 1024) g_wl[i] = 0xffffffffu;
    if (tid == 0) g_total = tot64;
}

// ---------------- kernel 2: persistent fused MLP (f32x2) --------------------
#define SMEM2_FLOATS (8192 + 32768 + 192 + 64 + 128 + 256 + 192 + 4096 + 8192 + 64 + 16)
#define SMEM2_BYTES  (SMEM2_FLOATS * 4)

__global__ void __launch_bounds__(256, 1) mlp_kernel(float* __restrict__ out)
{
    extern __shared__ float sm[];
    float* sW2 = sm;                  // 8192
    float* sW3 = sW2 + 8192;          // 32768
    float* sW1 = sW3 + 32768;         // 192
    float* sB1 = sW1 + 192;           // 64
    float* sB2 = sB1 + 64;            // 128
    float* sB3 = sB2 + 128;           // 256
    float* sX  = sB3 + 256;           // 192  (3 x 64)
    float* sH1 = sX + 192;            // 4096 (64 x 64)
    float* sH2 = sH1 + 4096;          // 8192 (128 x 64)
    int*  sMask = (int*)(sH2 + 8192); // 64
    int*  sOB   = sMask + 64;         // 16 (per 4-col unit: output base or -1)

    int tid = threadIdx.x;
    for (int i = tid; i < 8192; i += 256)  sW2[i] = g_w2f[i];
    for (int i = tid; i < 32768; i += 256) sW3[i] = g_w3f[i];
    if (tid < 192) sW1[tid] = g_w1f[tid];
    if (tid < 64)  sB1[tid] = g_b1f[tid];
    if (tid < 128) sB2[tid] = g_b2f[tid];
    sB3[tid] = g_b3f[tid];

    int nb = g_total >> 6;

    for (int bt = blockIdx.x; bt < nb; bt += gridDim.x) {
        __syncthreads();
        if (tid < 64) {
            unsigned e = g_wl[bt * 64 + tid];
            int seed = -1;
            if (e != 0xffffffffu) {
                seed = (int)(e >> 8);
                int gi = seed * UCAP + (int)(e & 255u);
                sX[tid] = g_uh[gi]; sX[64 + tid] = g_uy[gi]; sX[128 + tid] = g_uz[gi];
                sMask[tid] = (int)g_um[gi];
            } else {
                sX[tid] = 0.f; sX[64 + tid] = 0.f; sX[128 + tid] = 0.f; sMask[tid] = 0;
            }
            if ((tid & 3) == 0)
                sOB[tid >> 2] = (seed < 0) ? -1 : ((seed >> 10) * 1048576 + (seed & 1023) * 4);
        }
        __syncthreads();

        // ---- layer 1: 3 -> 64 ----
        {
            int o = tid >> 2, k0 = (tid & 3) << 4;
            float w0 = sW1[o * 3], w1 = sW1[o * 3 + 1], w2 = sW1[o * 3 + 2], bb = sB1[o];
#pragma unroll
            for (int j = 0; j < 16; j++) {
                int k = k0 + j;
                float v = bb + w0 * sX[k] + w1 * sX[64 + k] + w2 * sX[128 + k];
                sH1[o * 64 + k] = fmaxf(v, 0.f);
            }
        }
        __syncthreads();

        // ---- layer 2: 64 -> 128, f32x2, 4o x 8k per thread ----
        {
            int to = (tid >> 3) << 2, k0 = (tid & 7) << 3;
            ull acc[4][4];
#pragma unroll
            for (int i = 0; i < 4; i++)
#pragma unroll
                for (int q = 0; q < 4; q++) acc[i][q] = 0ull;
#pragma unroll 4
            for (int c4 = 0; c4 < 16; c4++) {
                int c = c4 << 2;
                ulonglong2 A[4][2];
#pragma unroll
                for (int cc = 0; cc < 4; cc++) {
                    A[cc][0] = *(const ulonglong2*)&sH1[(c + cc) * 64 + k0];
                    A[cc][1] = *(const ulonglong2*)&sH1[(c + cc) * 64 + k0 + 4];
                }
#pragma unroll
                for (int i = 0; i < 4; i++) {
                    float4 wv = *(const float4*)&sW2[(to + i) * 64 + c];
                    ull w0 = pack2(wv.x), w1 = pack2(wv.y), w2 = pack2(wv.z), w3 = pack2(wv.w);
                    acc[i][0] = fma2(w0, A[0][0].x, acc[i][0]);
                    acc[i][1] = fma2(w0, A[0][0].y, acc[i][1]);
                    acc[i][2] = fma2(w0, A[0][1].x, acc[i][2]);
                    acc[i][3] = fma2(w0, A[0][1].y, acc[i][3]);
                    acc[i][0] = fma2(w1, A[1][0].x, acc[i][0]);
                    acc[i][1] = fma2(w1, A[1][0].y, acc[i][1]);
                    acc[i][2] = fma2(w1, A[1][1].x, acc[i][2]);
                    acc[i][3] = fma2(w1, A[1][1].y, acc[i][3]);
                    acc[i][0] = fma2(w2, A[2][0].x, acc[i][0]);
                    acc[i][1] = fma2(w2, A[2][0].y, acc[i][1]);
                    acc[i][2] = fma2(w2, A[2][1].x, acc[i][2]);
                    acc[i][3] = fma2(w2, A[2][1].y, acc[i][3]);
                    acc[i][0] = fma2(w3, A[3][0].x, acc[i][0]);
                    acc[i][1] = fma2(w3, A[3][0].y, acc[i][1]);
                    acc[i][2] = fma2(w3, A[3][1].x, acc[i][2]);
                    acc[i][3] = fma2(w3, A[3][1].y, acc[i][3]);
                }
            }
#pragma unroll
            for (int i = 0; i < 4; i++) {
                float bb = sB2[to + i];
#pragma unroll
                for (int q = 0; q < 4; q++) {
                    float2 f = u2f(acc[i][q]);
                    float2 o2; o2.x = fmaxf(f.x + bb, 0.f); o2.y = fmaxf(f.y + bb, 0.f);
                    *(float2*)&sH2[(to + i) * 64 + k0 + 2 * q] = o2;
                }
            }
        }
        __syncthreads();

        // ---- layer 3: 128 -> 256, f32x2, 8o x 8k + depth-masked max + RED ---
        {
            int to = (tid >> 3) << 3, k0 = (tid & 7) << 3;
            ull acc[8][4];
#pragma unroll
            for (int i = 0; i < 8; i++)
#pragma unroll
                for (int q = 0; q < 4; q++) acc[i][q] = 0ull;
#pragma unroll 2
            for (int c4 = 0; c4 < 32; c4++) {
                int c = c4 << 2;
                ulonglong2 A[4][2];
#pragma unroll
                for (int cc = 0; cc < 4; cc++) {
                    A[cc][0] = *(const ulonglong2*)&sH2[(c + cc) * 64 + k0];
                    A[cc][1] = *(const ulonglong2*)&sH2[(c + cc) * 64 + k0 + 4];
                }
#pragma unroll
                for (int i = 0; i < 8; i++) {
                    float4 wv = *(const float4*)&sW3[(to + i) * 128 + c];
                    ull w0 = pack2(wv.x), w1 = pack2(wv.y), w2 = pack2(wv.z), w3 = pack2(wv.w);
                    acc[i][0] = fma2(w0, A[0][0].x, acc[i][0]);
                    acc[i][1] = fma2(w0, A[0][0].y, acc[i][1]);
                    acc[i][2] = fma2(w0, A[0][1].x, acc[i][2]);
                    acc[i][3] = fma2(w0, A[0][1].y, acc[i][3]);
                    acc[i][0] = fma2(w1, A[1][0].x, acc[i][0]);
                    acc[i][1] = fma2(w1, A[1][0].y, acc[i][1]);
                    acc[i][2] = fma2(w1, A[1][1].x, acc[i][2]);
                    acc[i][3] = fma2(w1, A[1][1].y, acc[i][3]);
                    acc[i][0] = fma2(w2, A[2][0].x, acc[i][0]);
                    acc[i][1] = fma2(w2, A[2][0].y, acc[i][1]);
                    acc[i][2] = fma2(w2, A[2][1].x, acc[i][2]);
                    acc[i][3] = fma2(w2, A[2][1].y, acc[i][3]);
                    acc[i][0] = fma2(w3, A[3][0].x, acc[i][0]);
                    acc[i][1] = fma2(w3, A[3][0].y, acc[i][1]);
                    acc[i][2] = fma2(w3, A[3][1].x, acc[i][2]);
                    acc[i][3] = fma2(w3, A[3][1].y, acc[i][3]);
                }
            }
            // epilogue: two 4-col units; per-unit depth-masked max + atomics
            float b3r[8];
#pragma unroll
            for (int i = 0; i < 8; i++) b3r[i] = sB3[to + i];
            int mk[8];
#pragma unroll
            for (int j = 0; j < 8; j++) mk[j] = sMask[k0 + j];
#pragma unroll
            for (int half = 0; half < 2; half++) {
                int ubH = mk[4 * half] | mk[4 * half + 1] | mk[4 * half + 2] | mk[4 * half + 3];
                int ob = sOB[(k0 >> 2) + half];
                if (ob < 0 || ubH == 0) continue;
                float vm[4][8];
#pragma unroll
                for (int d = 0; d < 4; d++)
#pragma unroll
                    for (int i = 0; i < 8; i++) vm[d][i] = 0.f;
#pragma unroll
                for (int qq = 0; qq < 2; qq++) {
                    int q = 2 * half + qq;
                    int m0 = mk[2 * q], m1 = mk[2 * q + 1];
#pragma unroll
                    for (int i = 0; i < 8; i++) {
                        float2 f = u2f(acc[i][q]);
                        float va = fmaxf(f.x + b3r[i], 0.f);
                        float vb = fmaxf(f.y + b3r[i], 0.f);
                        if (m0 & 1) vm[0][i] = fmaxf(vm[0][i], va);
                        if (m0 & 2) vm[1][i] = fmaxf(vm[1][i], va);
                        if (m0 & 4) vm[2][i] = fmaxf(vm[2][i], va);
                        if (m0 & 8) vm[3][i] = fmaxf(vm[3][i], va);
                        if (m1 & 1) vm[0][i] = fmaxf(vm[0][i], vb);
                        if (m1 & 2) vm[1][i] = fmaxf(vm[1][i], vb);
                        if (m1 & 4) vm[2][i] = fmaxf(vm[2][i], vb);
                        if (m1 & 8) vm[3][i] = fmaxf(vm[3][i], vb);
                    }
                }
#pragma unroll
                for (int d = 0; d < 4; d++) {
                    if ((ubH >> d) & 1) {
                        int* op = (int*)out + ob + d;
#pragma unroll
                        for (int i = 0; i < 8; i++)
                            atomicMax(op + (to + i) * 4096, __float_as_int(vm[d][i]));
                    }
                }
            }
        }
    }
}

// ---------------- launch ----------------------------------------------------
extern "C" void kernel_launch(void* const* d_in, const int* in_sizes, int n_in,
                              void* d_out, int out_size)
{
    const float* seed = (const float*)d_in[0];
    const float* pc   = (const float*)d_in[1];
    const float* vp   = (const float*)d_in[2];
    float* out = (float*)d_out;

    cudaFuncSetAttribute(mlp_kernel, cudaFuncAttributeMaxDynamicSharedMemorySize, SMEM2_BYTES);

    prep_kernel<<<512, 256>>>(pc,
        (const float*)d_in[3],  (const float*)d_in[4],  (const float*)d_in[5],
        (const float*)d_in[6],  (const float*)d_in[7],  (const float*)d_in[8],
        (const float*)d_in[9],  (const float*)d_in[10], (const float*)d_in[11],
        (const float*)d_in[12], (const float*)d_in[13], (const float*)d_in[14],
        (const float*)d_in[15], (const float*)d_in[16], (const float*)d_in[17],
        (const float*)d_in[18], (const float*)d_in[19], (const float*)d_in[20],
        out);
    group_kernel<<<NSEEDT / GW, 512>>>(seed, vp);
    pack_kernel<<<1, 1024>>>();
    mlp_kernel<<<152, 256, SMEM2_BYTES>>>(out);
}